// round 16
// baseline (speedup 1.0000x reference)
#include <cuda_runtime.h>
#include <cuda_bf16.h>
#include <cstdint>

#define T_      4
#define B_      32
#define N_      256
#define C_      384
#define H_      8
#define D_      48
#define BNROWS  8192
#define TBN     32768
#define NELEM   (TBN * C_)            // 12582912
#define SCALE_  0.051031036307982884f // 384^-0.5

// ---------------- scratch ----------------
__device__ uint4 g_x1_[NELEM / 8];        // bf16 x splits
__device__ uint4 g_x2_[NELEM / 8];
__device__ uint4 g_x3_[NELEM / 8];
__device__ uint4 g_w1_[4 * C_ * C_ / 8];  // bf16 weight splits (q,k,v,p)
__device__ uint4 g_w2_[4 * C_ * C_ / 8];
__device__ uint4 g_w3_[4 * C_ * C_ / 8];
__device__ uint4 g_sqb_[NELEM / 8];       // bf16 q spikes [t,bn,c]
__device__ uint4 g_kT_[NELEM / 8];        // bf16 k spikes TRANSPOSED [t,b,h,d,m]
__device__ uint4 g_vT_[NELEM / 8];        // bf16 v spikes TRANSPOSED [t,b,h,d,m]
__device__ uint4 g_attn_[NELEM / 4];      // f32 attn out (pre lif)
__device__ uint4 g_aspk_[NELEM / 8];      // bf16 attn spikes (proj input)
__device__ uint4 g_bm1_[8 * 256 * 256 / 8]; // bf16 bias split 1 [h][n][m]
__device__ uint4 g_bm2_[8 * 256 * 256 / 8]; // bf16 bias split 2

// ---------------- helpers ----------------
__device__ __forceinline__ uint32_t smem_u32(const void* p) {
    uint32_t a;
    asm("{ .reg .u64 t; cvta.to.shared.u64 t, %1; cvt.u32.u64 %0, t; }"
        : "=r"(a) : "l"(p));
    return a;
}
__device__ __forceinline__ void cp_async16(uint32_t saddr, const void* gaddr) {
    asm volatile("cp.async.cg.shared.global [%0], [%1], 16;" :: "r"(saddr), "l"(gaddr));
}
__device__ __forceinline__ void cp_commit() { asm volatile("cp.async.commit_group;"); }

__device__ __forceinline__ void ldsm_x4(uint32_t addr, uint32_t& r0, uint32_t& r1,
                                        uint32_t& r2, uint32_t& r3) {
    asm volatile("ldmatrix.sync.aligned.m8n8.x4.shared.b16 {%0,%1,%2,%3}, [%4];"
                 : "=r"(r0), "=r"(r1), "=r"(r2), "=r"(r3) : "r"(addr));
}
__device__ __forceinline__ void mma_bf16(float& c0, float& c1, float& c2, float& c3,
                                         uint32_t a0, uint32_t a1, uint32_t a2, uint32_t a3,
                                         uint32_t b0, uint32_t b1) {
    asm volatile("mma.sync.aligned.m16n8k16.row.col.f32.bf16.bf16.f32 "
                 "{%0,%1,%2,%3}, {%4,%5,%6,%7}, {%8,%9}, {%0,%1,%2,%3};"
                 : "+f"(c0), "+f"(c1), "+f"(c2), "+f"(c3)
                 : "r"(a0), "r"(a1), "r"(a2), "r"(a3), "r"(b0), "r"(b1));
}

#define SWZ128(o) ((o) ^ (((o) >> 3) & 0x70))

struct GArgs {
    const __nv_bfloat16* A[3];     // A splits
    const __nv_bfloat16* W[3][3];  // [branch][split]
    const float* bnp[3];           // BN params per branch
    void* dst[3];                  // output per branch
    int mode[3];                   // 0=f32 spikes, 2=bf16 normal, 3=bf16 transposed [t,b,h,d,m]
};

// ---------------- HMMA GEMM, kc-outer, 2-stage, fused BN/LIF ----------------
// 256 thr, 8 warps (2x4), warp tile 64x32, CTA tile 128x128, BK=32.
template<int NPROD>
__global__ __launch_bounds__(256, 2) void hmma_gemm(GArgs args)
{
    constexpr int STG = (NPROD == 3) ? 32768 : 49152;
    extern __shared__ char smem_raw[];
    const uint32_t sbase = smem_u32(smem_raw);
    const int tid = threadIdx.x, wid = tid >> 5, l = tid & 31;
    const int wm = wid >> 2, wn = wid & 3;
    const int m0 = blockIdx.x * 128;
    const int branch = blockIdx.y / 3;
    const int c0 = (blockIdx.y % 3) * 128;

    float acc[4][4][4];
    #pragma unroll
    for (int mt = 0; mt < 4; ++mt)
        #pragma unroll
        for (int nt = 0; nt < 4; ++nt)
            #pragma unroll
            for (int r = 0; r < 4; ++r) acc[mt][nt][r] = 0.f;

    auto slot = [](int t) -> int {
        return (NPROD == 3) ? ((t == 0) ? 0 : t - 2) : t;
    };

    auto prefetch = [&](int kc, int buf) {
        #pragma unroll
        for (int t = 0; t < 6; ++t) {
            if (NPROD == 3 && (t == 1 || t == 2)) continue;
            const __nv_bfloat16* g = (t < 3) ? args.A[t] : args.W[branch][t - 3];
            #pragma unroll
            for (int it = 0; it < 2; ++it) {
                int idx = tid + it * 256;
                int row = idx >> 2, ch = idx & 3;
                const __nv_bfloat16* src;
                if (t < 3) {
                    int r = m0 + row;
                    src = g + (size_t)((r & 3) * BNROWS + (r >> 2)) * C_ + kc * 32 + ch * 8;
                } else {
                    src = g + (size_t)(c0 + row) * C_ + kc * 32 + ch * 8;
                }
                uint32_t dst = sbase + buf * STG + slot(t) * 8192
                             + row * 64 + ((ch * 16) ^ ((row & 6) << 3));
                cp_async16(dst, src);
            }
        }
        cp_commit();
    };

    prefetch(0, 0);
    prefetch(1, 1);

    for (int s = 0; s < 12; ++s) {
        if (s < 11) asm volatile("cp.async.wait_group 1;");
        else        asm volatile("cp.async.wait_group 0;");
        __syncthreads();

        const uint32_t sb = sbase + (s & 1) * STG;
        #pragma unroll
        for (int kk = 0; kk < 2; ++kk) {
            uint32_t bfrag[3][2][4];
            #pragma unroll
            for (int pb = 0; pb < 3; ++pb) {
                #pragma unroll
                for (int bt = 0; bt < 2; ++bt) {
                    uint32_t nrow = wn * 32 + bt * 16 + (l & 7) + ((l >> 4) << 3);
                    uint32_t ko = (uint32_t)(kk * 16 + ((l >> 3) & 1) * 8) * 2;
                    ldsm_x4(sb + slot(3 + pb) * 8192 + nrow * 64 + (ko ^ ((nrow & 6) << 3)),
                            bfrag[pb][bt][0], bfrag[pb][bt][1],
                            bfrag[pb][bt][2], bfrag[pb][bt][3]);
                }
            }
            #pragma unroll
            for (int pa = 0; pa < 3; ++pa) {
                if (NPROD == 3 && pa > 0) break;
                uint32_t a[4][4];
                #pragma unroll
                for (int mt = 0; mt < 4; ++mt) {
                    uint32_t row = wm * 64 + mt * 16 + (l & 15);
                    uint32_t ko = (uint32_t)(kk * 16 + (l >> 4) * 8) * 2;
                    ldsm_x4(sb + slot(pa) * 8192 + row * 64 + (ko ^ ((row & 6) << 3)),
                            a[mt][0], a[mt][1], a[mt][2], a[mt][3]);
                }
                #pragma unroll
                for (int pb = 0; pb < 3; ++pb) {
                    bool use = (NPROD == 3) ? true : (pa + pb <= 2);
                    if (!use) continue;
                    #pragma unroll
                    for (int mt = 0; mt < 4; ++mt)
                        #pragma unroll
                        for (int nt = 0; nt < 4; ++nt) {
                            uint32_t b0 = bfrag[pb][nt >> 1][(nt & 1) * 2 + 0];
                            uint32_t b1 = bfrag[pb][nt >> 1][(nt & 1) * 2 + 1];
                            mma_bf16(acc[mt][nt][0], acc[mt][nt][1],
                                     acc[mt][nt][2], acc[mt][nt][3],
                                     a[mt][0], a[mt][1], a[mt][2], a[mt][3], b0, b1);
                        }
                }
            }
        }
        __syncthreads();
        if (s + 2 < 12) prefetch(s + 2, s & 1);
    }

    // ---- epilogue: transpose to smem [col][row] pitch 132, BN + LIF ----
    float* eps = (float*)smem_raw;
    #pragma unroll
    for (int mt = 0; mt < 4; ++mt) {
        int r0r = wm * 64 + mt * 16 + (l >> 2);
        #pragma unroll
        for (int nt = 0; nt < 4; ++nt) {
            int cc = wn * 32 + nt * 8 + (l & 3) * 2;
            eps[(cc + 0) * 132 + r0r]     = acc[mt][nt][0];
            eps[(cc + 1) * 132 + r0r]     = acc[mt][nt][1];
            eps[(cc + 0) * 132 + r0r + 8] = acc[mt][nt][2];
            eps[(cc + 1) * 132 + r0r + 8] = acc[mt][nt][3];
        }
    }
    __syncthreads();

    const int mode = args.mode[branch];
    {
        const int c = tid & 127;
        const int half = tid >> 7;
        const int cg = c0 + c;
        const float* bnp = args.bnp[branch];
        const float gamma = bnp[cg], beta = bnp[C_ + cg];
        const float mean = bnp[2 * C_ + cg], var = bnp[3 * C_ + cg];
        const float sc = gamma * (1.0f / sqrtf(var + 1e-5f));
        const int bn0 = m0 >> 2;
        float* df = (float*)args.dst[branch];
        __nv_bfloat16* db = (__nv_bfloat16*)args.dst[branch];
        const __nv_bfloat16 bone = __float2bfloat16(1.0f);
        const __nv_bfloat16 bzero = __float2bfloat16(0.0f);
        for (int b = 0; b < 16; ++b) {
            const int bidx = half * 16 + b;
            float4 y4 = *(float4*)&eps[c * 132 + 4 * bidx];
            float ys[4] = {y4.x, y4.y, y4.z, y4.w};
            const int bn = bn0 + bidx;
            float v = 0.f;
            #pragma unroll
            for (int t = 0; t < 4; ++t) {
                float y = (ys[t] - mean) * sc + beta;
                float h = v + (y - v) * 0.5f;
                bool s = (h >= 1.0f);
                if (mode == 3) {
                    eps[c * 132 + 4 * bidx + t] = s ? 1.0f : 0.0f;
                } else {
                    size_t o = (size_t)(t * BNROWS + bn) * C_ + cg;
                    if (mode == 2) db[o] = s ? bone : bzero;
                    else           df[o] = s ? 1.0f : 0.0f;
                }
                v = s ? 0.f : h;
            }
        }
    }

    if (mode == 3) {
        // regroup: write [t][b][h][d][m] with 64B-contiguous m rows
        __syncthreads();
        const int bn0 = m0 >> 2;
        const int bb = bn0 >> 8;          // batch index (constant per CTA)
        const int n0 = bn0 & 255;         // m-offset of this CTA's 32 rows
        __nv_bfloat16* dstb = (__nv_bfloat16*)args.dst[branch];
        for (int task = tid; task < 512; task += 256) {
            const int c = task & 127;
            const int t = task >> 7;      // first pass t in {0,1}, second t in {2,3}
            const int cg = c0 + c;
            const int hh = cg / 48, dd = cg - hh * 48;
            unsigned short pk[32];
            #pragma unroll
            for (int bl = 0; bl < 32; ++bl) {
                __nv_bfloat16 bv = __float2bfloat16(eps[c * 132 + 4 * bl + t]);
                pk[bl] = *(unsigned short*)&bv;
            }
            __nv_bfloat16* dp = dstb
                + ((((size_t)(t * B_ + bb) * H_ + hh) * D_ + dd) * N_ + n0);
            #pragma unroll
            for (int q = 0; q < 4; ++q)
                *(uint4*)(dp + q * 8) = *(uint4*)&pk[q * 8];
        }
    }
}

// ---------------- split fp32 into 3 bf16 terms ----------------
__global__ __launch_bounds__(256) void convert3(
    const float* __restrict__ src, __nv_bfloat16* __restrict__ d1,
    __nv_bfloat16* __restrict__ d2, __nv_bfloat16* __restrict__ d3, int n)
{
    int i = blockIdx.x * 256 + threadIdx.x;
    if (i >= n) return;
    float x = src[i];
    __nv_bfloat16 b1 = __float2bfloat16(x);
    float r1 = x - __bfloat162float(b1);
    __nv_bfloat16 b2 = __float2bfloat16(r1);
    float r2 = r1 - __bfloat162float(b2);
    __nv_bfloat16 b3 = __float2bfloat16(r2);
    d1[i] = b1; d2[i] = b2; d3[i] = b3;
}

// ---------------- fused: split all 4 weights ----------------
struct W4 { const float* w[4]; };
__global__ __launch_bounds__(256) void convert3w(
    W4 ws, __nv_bfloat16* __restrict__ d1,
    __nv_bfloat16* __restrict__ d2, __nv_bfloat16* __restrict__ d3)
{
    int i = blockIdx.x * 256 + threadIdx.x;
    if (i >= 4 * C_ * C_) return;
    int br = i / (C_ * C_);
    float x = ws.w[br][i - br * (C_ * C_)];
    __nv_bfloat16 b1 = __float2bfloat16(x);
    float r1 = x - __bfloat162float(b1);
    __nv_bfloat16 b2 = __float2bfloat16(r1);
    float r2 = r1 - __bfloat162float(b2);
    __nv_bfloat16 b3 = __float2bfloat16(r2);
    d1[i] = b1; d2[i] = b2; d3[i] = b3;
}

// ---------------- build bf16 Toeplitz bias matrices (2-term split) ----------------
__global__ __launch_bounds__(256) void biasmat(
    const float* __restrict__ rel, __nv_bfloat16* __restrict__ bm1,
    __nv_bfloat16* __restrict__ bm2)
{
    int i = blockIdx.x * 256 + threadIdx.x;   // [h][n][m]
    if (i >= 8 * 256 * 256) return;
    int h = i >> 16, n = (i >> 8) & 255, m = i & 255;
    float r = rel[(n - m + 255) * H_ + h];
    __nv_bfloat16 b1 = __float2bfloat16(r);
    float r2 = r - __bfloat162float(b1);
    bm1[i] = b1;
    bm2[i] = __float2bfloat16(r2);
}

// ---------------- LIF over T -> bf16 spikes, 4 elems/thread ----------------
__global__ __launch_bounds__(256) void attn_lif_pack(
    const float* __restrict__ In, __nv_bfloat16* __restrict__ Out)
{
    int i4 = (blockIdx.x * 256 + threadIdx.x) * 4;
    if (i4 >= BNROWS * C_) return;
    const __nv_bfloat16 one = __float2bfloat16(1.0f);
    const __nv_bfloat16 zero = __float2bfloat16(0.0f);
    float v0 = 0.f, v1 = 0.f, v2 = 0.f, v3 = 0.f;
    #pragma unroll
    for (int t = 0; t < 4; ++t) {
        float4 x = *(const float4*)(In + (size_t)t * BNROWS * C_ + i4);
        float h0 = v0 + (x.x - v0) * 0.5f;
        float h1 = v1 + (x.y - v1) * 0.5f;
        float h2 = v2 + (x.z - v2) * 0.5f;
        float h3 = v3 + (x.w - v3) * 0.5f;
        bool s0 = (h0 >= 1.0f), s1 = (h1 >= 1.0f), s2 = (h2 >= 1.0f), s3 = (h3 >= 1.0f);
        v0 = s0 ? 0.f : h0; v1 = s1 ? 0.f : h1;
        v2 = s2 ? 0.f : h2; v3 = s3 ? 0.f : h3;
        __nv_bfloat162 p0, p1;
        p0.x = s0 ? one : zero; p0.y = s1 ? one : zero;
        p1.x = s2 ? one : zero; p1.y = s3 ? one : zero;
        uint2 pk;
        pk.x = *(uint32_t*)&p0; pk.y = *(uint32_t*)&p1;
        *(uint2*)(Out + (size_t)t * BNROWS * C_ + i4) = pk;
    }
}

// ---------------- attention via HMMA, factorized S-path, all-cp.async prologue ----------------
// out[n][d] = SCALE * ( Q[n,:]·(K^T V)[:,d] + sum_m (bias1+bias2)[n][m] V[m][d] )
// K^T/V^T arrive pre-transposed from the GEMM epilogue: layout [t][b][h][d][m].
// smem layout (extent 96256 -> 2 CTA/SM):
//   VTB [0,24576) | KTB [24576,49152) | QB [57344,90112) | KTVB [90112,96256)
//   AB0 alias [24576,57344)   AB1 alias [57344,90112)
#define VTB_   (sbase + 0u)
#define KTB_   (sbase + 24576u)
#define QB_    (sbase + 57344u)
#define KTVB_  (sbase + 90112u)
__global__ __launch_bounds__(256, 2) void attn_mma(
    const __nv_bfloat16* __restrict__ Qs, const __nv_bfloat16* __restrict__ KT,
    const __nv_bfloat16* __restrict__ VT, const __nv_bfloat16* __restrict__ bm1,
    const __nv_bfloat16* __restrict__ bm2, float* __restrict__ AOut)
{
    extern __shared__ char smem_raw[];
    const uint32_t sbase = smem_u32(smem_raw);

    const int tid = threadIdx.x, wid = tid >> 5, l = tid & 31;
    const int bx = blockIdx.x;
    const int h = bx & 7;
    const int b = (bx >> 3) & 31;
    const int t = bx >> 8;
    const int r0 = t * BNROWS + b * N_;
    // base of this (t,b,h) slab in the transposed layout: [t][b][h][d][m]
    const size_t tbase = (((size_t)(t * B_ + b) * H_ + h) * D_) * N_;

    auto abuf = [&](int c) -> uint32_t {
        return (c & 1) ? (sbase + 57344u) : (sbase + 24576u);
    };
    auto issue_bias = [&](int c) {
        const __nv_bfloat16* bm = (c < 4) ? bm1 : bm2;
        int mc = c & 3;
        uint32_t dstb = abuf(c);
        #pragma unroll
        for (int it = 0; it < 8; ++it) {
            int g = tid + it * 256;            // 2048 granules
            int n = g >> 3, ch = g & 7;
            const __nv_bfloat16* src = bm + (size_t)((h * 256 + n) * 256 + mc * 64 + ch * 8);
            cp_async16(dstb + SWZ128((uint32_t)(n * 128 + ch * 16)), src);
        }
        cp_commit();
    };

    // prologue: Q tile (group 0)
    #pragma unroll
    for (int it = 0; it < 6; ++it) {
        int g = tid + it * 256;
        int n = g / 6, ch = g % 6;
        cp_async16(QB_ + SWZ128((uint32_t)(n * 128 + ch * 16)),
                   Qs + (size_t)(r0 + n) * C_ + h * D_ + ch * 8);
    }
    cp_commit();
    // K^T (group 1) and V^T (group 2): 1536 granules each, rows d of 512B
    #pragma unroll
    for (int it = 0; it < 6; ++it) {
        int g = tid + it * 256;
        int d = g >> 5, mg = g & 31;
        cp_async16(KTB_ + d * 512 + (((uint32_t)mg * 16) ^ (((uint32_t)d & 7) << 4)),
                   KT + tbase + (size_t)d * N_ + mg * 8);
    }
    cp_commit();
    #pragma unroll
    for (int it = 0; it < 6; ++it) {
        int g = tid + it * 256;
        int d = g >> 5, mg = g & 31;
        cp_async16(VTB_ + d * 512 + (((uint32_t)mg * 16) ^ (((uint32_t)d & 7) << 4)),
                   VT + tbase + (size_t)d * N_ + mg * 8);
    }
    cp_commit();

    asm volatile("cp.async.wait_group 0;");
    __syncthreads();

    // ---- stage 1: KTV[d'][d] = sum_m K[m][d'] V[m][d], write transposed ----
    for (int u = wid; u < 9; u += 8) {
        const int mt = u / 3, dp = u % 3;
        float ka[2][4];
        #pragma unroll
        for (int q = 0; q < 2; ++q)
            #pragma unroll
            for (int r = 0; r < 4; ++r) ka[q][r] = 0.f;
        for (int kidx = 0; kidx < 16; ++kidx) {
            uint32_t a0, a1, a2, a3, b0, b1, b2, b3;
            uint32_t arow = mt * 16 + (l & 15);
            uint32_t ko = (uint32_t)(kidx * 16 + (l >> 4) * 8) * 2;
            ldsm_x4(KTB_ + arow * 512 + (ko ^ ((arow & 7) << 4)), a0, a1, a2, a3);
            uint32_t brow = dp * 16 + (l & 7) + ((l >> 4) << 3);
            uint32_t kb = (uint32_t)(kidx * 16 + ((l >> 3) & 1) * 8) * 2;
            ldsm_x4(VTB_ + brow * 512 + (kb ^ ((brow & 7) << 4)), b0, b1, b2, b3);
            mma_bf16(ka[0][0], ka[0][1], ka[0][2], ka[0][3], a0, a1, a2, a3, b0, b1);
            mma_bf16(ka[1][0], ka[1][1], ka[1][2], ka[1][3], a0, a1, a2, a3, b2, b3);
        }
        int r = mt * 16 + (l >> 2);
        #pragma unroll
        for (int q = 0; q < 2; ++q) {
            int d = dp * 16 + q * 8 + (l & 3) * 2;
            __nv_bfloat16 v0 = __float2bfloat16(ka[q][0]);
            __nv_bfloat16 v1 = __float2bfloat16(ka[q][1]);
            __nv_bfloat16 v2 = __float2bfloat16(ka[q][2]);
            __nv_bfloat16 v3 = __float2bfloat16(ka[q][3]);
            char* kb = smem_raw + 90112;
            *(unsigned short*)(kb + SWZ128((uint32_t)((d + 0) * 128 + r * 2)))       = *(unsigned short*)&v0;
            *(unsigned short*)(kb + SWZ128((uint32_t)((d + 1) * 128 + r * 2)))       = *(unsigned short*)&v1;
            *(unsigned short*)(kb + SWZ128((uint32_t)((d + 0) * 128 + (r + 8) * 2))) = *(unsigned short*)&v2;
            *(unsigned short*)(kb + SWZ128((uint32_t)((d + 1) * 128 + (r + 8) * 2))) = *(unsigned short*)&v3;
        }
    }
    __syncthreads();           // KTB reads complete -> AB0 (alias) may be filled
    issue_bias(0);             // pending: [b0]

    float acc[2][6][4];
    #pragma unroll
    for (int mt = 0; mt < 2; ++mt)
        #pragma unroll
        for (int nt = 0; nt < 6; ++nt)
            #pragma unroll
            for (int r = 0; r < 4; ++r) acc[mt][nt][r] = 0.f;

    // ---- stage 2: acc += Q[n][d'] * KTV[d'][d]  (Q already resident) ----
    #pragma unroll
    for (int kk = 0; kk < 3; ++kk) {
        uint32_t a[2][4], bfr[3][4];
        #pragma unroll
        for (int mt = 0; mt < 2; ++mt) {
            uint32_t row = wid * 32 + mt * 16 + (l & 15);
            uint32_t byte = row * 128 + (uint32_t)(kk * 16 + (l >> 4) * 8) * 2;
            ldsm_x4(QB_ + SWZ128(byte), a[mt][0], a[mt][1], a[mt][2], a[mt][3]);
        }
        #pragma unroll
        for (int bt = 0; bt < 3; ++bt) {
            uint32_t nrow = bt * 16 + (l & 7) + ((l >> 4) << 3);
            uint32_t byte = nrow * 128 + (uint32_t)(kk * 16 + ((l >> 3) & 1) * 8) * 2;
            ldsm_x4(KTVB_ + SWZ128(byte), bfr[bt][0], bfr[bt][1], bfr[bt][2], bfr[bt][3]);
        }
        #pragma unroll
        for (int mt = 0; mt < 2; ++mt)
            #pragma unroll
            for (int nt = 0; nt < 6; ++nt) {
                uint32_t b0 = bfr[nt >> 1][(nt & 1) * 2 + 0];
                uint32_t b1 = bfr[nt >> 1][(nt & 1) * 2 + 1];
                mma_bf16(acc[mt][nt][0], acc[mt][nt][1], acc[mt][nt][2], acc[mt][nt][3],
                         a[mt][0], a[mt][1], a[mt][2], a[mt][3], b0, b1);
            }
    }
    __syncthreads();           // QB/KTVB reads done -> AB1 (alias over QB) may be filled
    issue_bias(1);             // pending: [b0, b1]

    // ---- bias chunks: acc += bias_chunk[n][64m] * V[m][d] ----
    for (int c = 0; c < 8; ++c) {
        const int mc = c & 3;
        if (c < 7) asm volatile("cp.async.wait_group 1;");
        else       asm volatile("cp.async.wait_group 0;");
        __syncthreads();

        const uint32_t ab = abuf(c);
        #pragma unroll
        for (int kk = 0; kk < 4; ++kk) {
            uint32_t a[2][4], bfr[3][4];
            #pragma unroll
            for (int mt = 0; mt < 2; ++mt) {
                uint32_t row = wid * 32 + mt * 16 + (l & 15);
                uint32_t byte = row * 128 + (uint32_t)(kk * 16 + (l >> 4) * 8) * 2;
                ldsm_x4(ab + SWZ128(byte), a[mt][0], a[mt][1], a[mt][2], a[mt][3]);
            }
            #pragma unroll
            for (int bt = 0; bt < 3; ++bt) {
                uint32_t nrow = bt * 16 + (l & 7) + ((l >> 4) << 3);
                uint32_t k = mc * 64 + kk * 16 + ((l >> 3) & 1) * 8;
                uint32_t addr = VTB_ + nrow * 512 + ((k * 2) ^ ((nrow & 7) << 4));
                ldsm_x4(addr, bfr[bt][0], bfr[bt][1], bfr[bt][2], bfr[bt][3]);
            }
            #pragma unroll
            for (int mt = 0; mt < 2; ++mt)
                #pragma unroll
                for (int nt = 0; nt < 6; ++nt) {
                    uint32_t b0 = bfr[nt >> 1][(nt & 1) * 2 + 0];
                    uint32_t b1 = bfr[nt >> 1][(nt & 1) * 2 + 1];
                    mma_bf16(acc[mt][nt][0], acc[mt][nt][1], acc[mt][nt][2], acc[mt][nt][3],
                             a[mt][0], a[mt][1], a[mt][2], a[mt][3], b0, b1);
                }
        }
        __syncthreads();
        if (c + 2 < 8) issue_bias(c + 2);
    }

    // epilogue: scale + store f32
    #pragma unroll
    for (int mt = 0; mt < 2; ++mt) {
        int n = wid * 32 + mt * 16 + (l >> 2);
        #pragma unroll
        for (int nt = 0; nt < 6; ++nt) {
            int d = nt * 8 + (l & 3) * 2;
            float* dst = AOut + (size_t)(r0 + n) * C_ + h * D_ + d;
            *(float2*)dst = make_float2(acc[mt][nt][0] * SCALE_, acc[mt][nt][1] * SCALE_);
            float* dst2 = dst + (size_t)8 * C_;
            *(float2*)dst2 = make_float2(acc[mt][nt][2] * SCALE_, acc[mt][nt][3] * SCALE_);
        }
    }
}

// ---------------- launch ----------------
extern "C" void kernel_launch(void* const* d_in, const int* in_sizes, int n_in,
                              void* d_out, int out_size)
{
    const float* x    = (const float*)d_in[0];
    const float* w_q  = (const float*)d_in[1];
    const float* w_k  = (const float*)d_in[2];
    const float* w_v  = (const float*)d_in[3];
    const float* w_p  = (const float*)d_in[4];
    const float* bn_q = (const float*)d_in[5];
    const float* bn_k = (const float*)d_in[6];
    const float* bn_v = (const float*)d_in[7];
    const float* bn_p = (const float*)d_in[8];
    const float* rel  = (const float*)d_in[9];
    float* out = (float*)d_out;

    __nv_bfloat16 *x1, *x2, *x3, *w1, *w2, *w3, *sqb, *kT, *vT, *aspk, *bm1, *bm2;
    float *attn;
    cudaGetSymbolAddress((void**)&x1, g_x1_);
    cudaGetSymbolAddress((void**)&x2, g_x2_);
    cudaGetSymbolAddress((void**)&x3, g_x3_);
    cudaGetSymbolAddress((void**)&w1, g_w1_);
    cudaGetSymbolAddress((void**)&w2, g_w2_);
    cudaGetSymbolAddress((void**)&w3, g_w3_);
    cudaGetSymbolAddress((void**)&sqb, g_sqb_);
    cudaGetSymbolAddress((void**)&kT, g_kT_);
    cudaGetSymbolAddress((void**)&vT, g_vT_);
    cudaGetSymbolAddress((void**)&attn, g_attn_);
    cudaGetSymbolAddress((void**)&aspk, g_aspk_);
    cudaGetSymbolAddress((void**)&bm1, g_bm1_);
    cudaGetSymbolAddress((void**)&bm2, g_bm2_);

    const int GSMEM6 = 98304;   // 2 x 48KB -> 2 CTA/SM
    const int GSMEM3 = 69632;   // 2 x 32KB + epilogue 67.6KB extent -> 3 CTA/SM
    const int ASMEM  = 96256;   // -> 2 CTA/SM
    cudaFuncSetAttribute(hmma_gemm<6>, cudaFuncAttributeMaxDynamicSharedMemorySize, GSMEM6);
    cudaFuncSetAttribute(hmma_gemm<3>, cudaFuncAttributeMaxDynamicSharedMemorySize, GSMEM3);
    cudaFuncSetAttribute(attn_mma,     cudaFuncAttributeMaxDynamicSharedMemorySize, ASMEM);

    const int WW = C_ * C_;

    convert3<<<(NELEM + 255) / 256, 256>>>(x, x1, x2, x3, NELEM);
    W4 ws; ws.w[0] = w_q; ws.w[1] = w_k; ws.w[2] = w_v; ws.w[3] = w_p;
    convert3w<<<(4 * WW + 255) / 256, 256>>>(ws, w1, w2, w3);
    biasmat<<<(8 * 256 * 256 + 255) / 256, 256>>>(rel, bm1, bm2);

    // fused QKV GEMM + BN + LIF (q normal bf16; k,v transposed bf16)
    GArgs ga;
    ga.A[0] = x1; ga.A[1] = x2; ga.A[2] = x3;
    ga.W[0][0] = w1 + 0 * WW; ga.W[0][1] = w2 + 0 * WW; ga.W[0][2] = w3 + 0 * WW;
    ga.W[1][0] = w1 + 1 * WW; ga.W[1][1] = w2 + 1 * WW; ga.W[1][2] = w3 + 1 * WW;
    ga.W[2][0] = w1 + 2 * WW; ga.W[2][1] = w2 + 2 * WW; ga.W[2][2] = w3 + 2 * WW;
    ga.bnp[0] = bn_q; ga.bnp[1] = bn_k; ga.bnp[2] = bn_v;
    ga.dst[0] = sqb; ga.dst[1] = kT; ga.dst[2] = vT;
    ga.mode[0] = 2; ga.mode[1] = 3; ga.mode[2] = 3;
    hmma_gemm<6><<<dim3(TBN / 128, 9), 256, GSMEM6>>>(ga);

    attn_mma<<<T_ * B_ * H_, 256, ASMEM>>>(sqb, kT, vT, bm1, bm2, attn);

    attn_lif_pack<<<(BNROWS * C_ / 4 + 255) / 256, 256>>>(attn, aspk);

    // proj GEMM (binary A exact in bf16 -> 3 products) writes final spikes
    GArgs gp;
    gp.A[0] = aspk; gp.A[1] = aspk; gp.A[2] = aspk;
    gp.W[0][0] = w1 + 3 * WW; gp.W[0][1] = w2 + 3 * WW; gp.W[0][2] = w3 + 3 * WW;
    gp.W[1][0] = gp.W[0][0]; gp.W[1][1] = gp.W[0][1]; gp.W[1][2] = gp.W[0][2];
    gp.W[2][0] = gp.W[0][0]; gp.W[2][1] = gp.W[0][1]; gp.W[2][2] = gp.W[0][2];
    gp.bnp[0] = bn_p; gp.bnp[1] = bn_p; gp.bnp[2] = bn_p;
    gp.dst[0] = out; gp.dst[1] = out; gp.dst[2] = out;
    gp.mode[0] = 0; gp.mode[1] = 0; gp.mode[2] = 0;
    hmma_gemm<3><<<dim3(TBN / 128, 3), 256, GSMEM3>>>(gp);
}

// round 17
// speedup vs baseline: 1.0375x; 1.0375x over previous
#include <cuda_runtime.h>
#include <cuda_bf16.h>
#include <cstdint>

#define T_      4
#define B_      32
#define N_      256
#define C_      384
#define H_      8
#define D_      48
#define BNROWS  8192
#define TBN     32768
#define NELEM   (TBN * C_)            // 12582912
#define SCALE_  0.051031036307982884f // 384^-0.5

// ---------------- scratch ----------------
__device__ uint4 g_x1_[NELEM / 8];        // bf16 x splits
__device__ uint4 g_x2_[NELEM / 8];
__device__ uint4 g_x3_[NELEM / 8];
__device__ uint4 g_w1_[4 * C_ * C_ / 8];  // bf16 weight splits (q,k,v,p)
__device__ uint4 g_w2_[4 * C_ * C_ / 8];
__device__ uint4 g_w3_[4 * C_ * C_ / 8];
__device__ uint4 g_sqb_[NELEM / 8];       // bf16 q spikes
__device__ uint4 g_skb_[NELEM / 8];       // bf16 k spikes
__device__ uint4 g_svb_[NELEM / 8];       // bf16 v spikes
__device__ uint4 g_attn_[NELEM / 4];      // f32 attn out (pre lif)
__device__ uint4 g_aspk_[NELEM / 8];      // bf16 attn spikes (proj input)
__device__ uint4 g_bm1_[8 * 256 * 256 / 8]; // bf16 bias split 1 [h][n][m]
__device__ uint4 g_bm2_[8 * 256 * 256 / 8]; // bf16 bias split 2

// ---------------- helpers ----------------
__device__ __forceinline__ uint32_t smem_u32(const void* p) {
    uint32_t a;
    asm("{ .reg .u64 t; cvta.to.shared.u64 t, %1; cvt.u32.u64 %0, t; }"
        : "=r"(a) : "l"(p));
    return a;
}
__device__ __forceinline__ void cp_async16(uint32_t saddr, const void* gaddr) {
    asm volatile("cp.async.cg.shared.global [%0], [%1], 16;" :: "r"(saddr), "l"(gaddr));
}
__device__ __forceinline__ void cp_commit() { asm volatile("cp.async.commit_group;"); }

__device__ __forceinline__ void ldsm_x4(uint32_t addr, uint32_t& r0, uint32_t& r1,
                                        uint32_t& r2, uint32_t& r3) {
    asm volatile("ldmatrix.sync.aligned.m8n8.x4.shared.b16 {%0,%1,%2,%3}, [%4];"
                 : "=r"(r0), "=r"(r1), "=r"(r2), "=r"(r3) : "r"(addr));
}
__device__ __forceinline__ void mma_bf16(float& c0, float& c1, float& c2, float& c3,
                                         uint32_t a0, uint32_t a1, uint32_t a2, uint32_t a3,
                                         uint32_t b0, uint32_t b1) {
    asm volatile("mma.sync.aligned.m16n8k16.row.col.f32.bf16.bf16.f32 "
                 "{%0,%1,%2,%3}, {%4,%5,%6,%7}, {%8,%9}, {%0,%1,%2,%3};"
                 : "+f"(c0), "+f"(c1), "+f"(c2), "+f"(c3)
                 : "r"(a0), "r"(a1), "r"(a2), "r"(a3), "r"(b0), "r"(b1));
}

#define SWZ128(o) ((o) ^ (((o) >> 3) & 0x70))

struct GArgs {
    const __nv_bfloat16* A[3];     // A splits
    const __nv_bfloat16* W[3][3];  // [branch][split]
    const float* bnp[3];           // BN params per branch
    void* dst[3];                  // output per branch
    int mode[3];                   // 0=f32 spikes, 2=bf16 spikes
};

// ---------------- HMMA GEMM, kc-outer, 2-stage, fused BN/LIF ----------------
// 256 thr, 8 warps (2x4), warp tile 64x32, CTA tile 128x128, BK=32.
template<int NPROD>
__global__ __launch_bounds__(256, 2) void hmma_gemm(GArgs args)
{
    constexpr int STG = (NPROD == 3) ? 32768 : 49152;
    extern __shared__ char smem_raw[];
    const uint32_t sbase = smem_u32(smem_raw);
    const int tid = threadIdx.x, wid = tid >> 5, l = tid & 31;
    const int wm = wid >> 2, wn = wid & 3;
    const int m0 = blockIdx.x * 128;
    const int branch = blockIdx.y / 3;
    const int c0 = (blockIdx.y % 3) * 128;

    float acc[4][4][4];
    #pragma unroll
    for (int mt = 0; mt < 4; ++mt)
        #pragma unroll
        for (int nt = 0; nt < 4; ++nt)
            #pragma unroll
            for (int r = 0; r < 4; ++r) acc[mt][nt][r] = 0.f;

    auto slot = [](int t) -> int {
        return (NPROD == 3) ? ((t == 0) ? 0 : t - 2) : t;
    };

    auto prefetch = [&](int kc, int buf) {
        #pragma unroll
        for (int t = 0; t < 6; ++t) {
            if (NPROD == 3 && (t == 1 || t == 2)) continue;
            const __nv_bfloat16* g = (t < 3) ? args.A[t] : args.W[branch][t - 3];
            #pragma unroll
            for (int it = 0; it < 2; ++it) {
                int idx = tid + it * 256;
                int row = idx >> 2, ch = idx & 3;
                const __nv_bfloat16* src;
                if (t < 3) {
                    int r = m0 + row;
                    src = g + (size_t)((r & 3) * BNROWS + (r >> 2)) * C_ + kc * 32 + ch * 8;
                } else {
                    src = g + (size_t)(c0 + row) * C_ + kc * 32 + ch * 8;
                }
                uint32_t dst = sbase + buf * STG + slot(t) * 8192
                             + row * 64 + ((ch * 16) ^ ((row & 6) << 3));
                cp_async16(dst, src);
            }
        }
        cp_commit();
    };

    prefetch(0, 0);
    prefetch(1, 1);

    for (int s = 0; s < 12; ++s) {
        if (s < 11) asm volatile("cp.async.wait_group 1;");
        else        asm volatile("cp.async.wait_group 0;");
        __syncthreads();

        const uint32_t sb = sbase + (s & 1) * STG;
        #pragma unroll
        for (int kk = 0; kk < 2; ++kk) {
            uint32_t bfrag[3][2][4];
            #pragma unroll
            for (int pb = 0; pb < 3; ++pb) {
                #pragma unroll
                for (int bt = 0; bt < 2; ++bt) {
                    uint32_t nrow = wn * 32 + bt * 16 + (l & 7) + ((l >> 4) << 3);
                    uint32_t ko = (uint32_t)(kk * 16 + ((l >> 3) & 1) * 8) * 2;
                    ldsm_x4(sb + slot(3 + pb) * 8192 + nrow * 64 + (ko ^ ((nrow & 6) << 3)),
                            bfrag[pb][bt][0], bfrag[pb][bt][1],
                            bfrag[pb][bt][2], bfrag[pb][bt][3]);
                }
            }
            #pragma unroll
            for (int pa = 0; pa < 3; ++pa) {
                if (NPROD == 3 && pa > 0) break;
                uint32_t a[4][4];
                #pragma unroll
                for (int mt = 0; mt < 4; ++mt) {
                    uint32_t row = wm * 64 + mt * 16 + (l & 15);
                    uint32_t ko = (uint32_t)(kk * 16 + (l >> 4) * 8) * 2;
                    ldsm_x4(sb + slot(pa) * 8192 + row * 64 + (ko ^ ((row & 6) << 3)),
                            a[mt][0], a[mt][1], a[mt][2], a[mt][3]);
                }
                #pragma unroll
                for (int pb = 0; pb < 3; ++pb) {
                    bool use = (NPROD == 3) ? true : (pa + pb <= 2);
                    if (!use) continue;
                    #pragma unroll
                    for (int mt = 0; mt < 4; ++mt)
                        #pragma unroll
                        for (int nt = 0; nt < 4; ++nt) {
                            uint32_t b0 = bfrag[pb][nt >> 1][(nt & 1) * 2 + 0];
                            uint32_t b1 = bfrag[pb][nt >> 1][(nt & 1) * 2 + 1];
                            mma_bf16(acc[mt][nt][0], acc[mt][nt][1],
                                     acc[mt][nt][2], acc[mt][nt][3],
                                     a[mt][0], a[mt][1], a[mt][2], a[mt][3], b0, b1);
                        }
                }
            }
        }
        __syncthreads();
        if (s + 2 < 12) prefetch(s + 2, s & 1);
    }

    // ---- epilogue: transpose to smem [col][row] pitch 132, BN + LIF ----
    float* eps = (float*)smem_raw;
    #pragma unroll
    for (int mt = 0; mt < 4; ++mt) {
        int r0r = wm * 64 + mt * 16 + (l >> 2);
        #pragma unroll
        for (int nt = 0; nt < 4; ++nt) {
            int cc = wn * 32 + nt * 8 + (l & 3) * 2;
            eps[(cc + 0) * 132 + r0r]     = acc[mt][nt][0];
            eps[(cc + 1) * 132 + r0r]     = acc[mt][nt][1];
            eps[(cc + 0) * 132 + r0r + 8] = acc[mt][nt][2];
            eps[(cc + 1) * 132 + r0r + 8] = acc[mt][nt][3];
        }
    }
    __syncthreads();

    {
        const int c = tid & 127;
        const int half = tid >> 7;
        const int cg = c0 + c;
        const float* bnp = args.bnp[branch];
        const float gamma = bnp[cg], beta = bnp[C_ + cg];
        const float mean = bnp[2 * C_ + cg], var = bnp[3 * C_ + cg];
        const float sc = gamma * (1.0f / sqrtf(var + 1e-5f));
        const int bn0 = m0 >> 2;
        const int mode = args.mode[branch];
        float* df = (float*)args.dst[branch];
        __nv_bfloat16* db = (__nv_bfloat16*)args.dst[branch];
        const __nv_bfloat16 bone = __float2bfloat16(1.0f);
        const __nv_bfloat16 bzero = __float2bfloat16(0.0f);
        for (int b = 0; b < 16; ++b) {
            const int bidx = half * 16 + b;
            float4 y4 = *(float4*)&eps[c * 132 + 4 * bidx];
            float ys[4] = {y4.x, y4.y, y4.z, y4.w};
            const int bn = bn0 + bidx;
            float v = 0.f;
            #pragma unroll
            for (int t = 0; t < 4; ++t) {
                float y = (ys[t] - mean) * sc + beta;
                float h = v + (y - v) * 0.5f;
                bool s = (h >= 1.0f);
                size_t o = (size_t)(t * BNROWS + bn) * C_ + cg;
                if (mode == 2) db[o] = s ? bone : bzero;
                else           df[o] = s ? 1.0f : 0.0f;
                v = s ? 0.f : h;
            }
        }
    }
}

// ---------------- split fp32 into 3 bf16 terms, 4 elems/thread ----------------
__global__ __launch_bounds__(256) void convert3(
    const float* __restrict__ src, __nv_bfloat16* __restrict__ d1,
    __nv_bfloat16* __restrict__ d2, __nv_bfloat16* __restrict__ d3, int n)
{
    int i4 = (blockIdx.x * 256 + threadIdx.x) * 4;
    if (i4 >= n) return;
    float4 x = *(const float4*)(src + i4);
    float xs[4] = {x.x, x.y, x.z, x.w};
    unsigned short p1[4], p2[4], p3[4];
    #pragma unroll
    for (int e = 0; e < 4; ++e) {
        float v = xs[e];
        __nv_bfloat16 b1 = __float2bfloat16(v);
        float r1 = v - __bfloat162float(b1);
        __nv_bfloat16 b2 = __float2bfloat16(r1);
        float r2 = r1 - __bfloat162float(b2);
        __nv_bfloat16 b3 = __float2bfloat16(r2);
        p1[e] = *(unsigned short*)&b1;
        p2[e] = *(unsigned short*)&b2;
        p3[e] = *(unsigned short*)&b3;
    }
    *(uint2*)(d1 + i4) = *(uint2*)p1;
    *(uint2*)(d2 + i4) = *(uint2*)p2;
    *(uint2*)(d3 + i4) = *(uint2*)p3;
}

// ---------------- fused: split all 4 weights, 4 elems/thread ----------------
struct W4 { const float* w[4]; };
__global__ __launch_bounds__(256) void convert3w(
    W4 ws, __nv_bfloat16* __restrict__ d1,
    __nv_bfloat16* __restrict__ d2, __nv_bfloat16* __restrict__ d3)
{
    int i4 = (blockIdx.x * 256 + threadIdx.x) * 4;
    if (i4 >= 4 * C_ * C_) return;
    int br = i4 / (C_ * C_);                // C_*C_ divisible by 4 -> same branch
    float4 x = *(const float4*)(ws.w[br] + (i4 - br * (C_ * C_)));
    float xs[4] = {x.x, x.y, x.z, x.w};
    unsigned short p1[4], p2[4], p3[4];
    #pragma unroll
    for (int e = 0; e < 4; ++e) {
        float v = xs[e];
        __nv_bfloat16 b1 = __float2bfloat16(v);
        float r1 = v - __bfloat162float(b1);
        __nv_bfloat16 b2 = __float2bfloat16(r1);
        float r2 = r1 - __bfloat162float(b2);
        __nv_bfloat16 b3 = __float2bfloat16(r2);
        p1[e] = *(unsigned short*)&b1;
        p2[e] = *(unsigned short*)&b2;
        p3[e] = *(unsigned short*)&b3;
    }
    *(uint2*)(d1 + i4) = *(uint2*)p1;
    *(uint2*)(d2 + i4) = *(uint2*)p2;
    *(uint2*)(d3 + i4) = *(uint2*)p3;
}

// ---------------- build bf16 Toeplitz bias matrices (2-term split) ----------------
__global__ __launch_bounds__(256) void biasmat(
    const float* __restrict__ rel, __nv_bfloat16* __restrict__ bm1,
    __nv_bfloat16* __restrict__ bm2)
{
    int i = blockIdx.x * 256 + threadIdx.x;   // [h][n][m]
    if (i >= 8 * 256 * 256) return;
    int h = i >> 16, n = (i >> 8) & 255, m = i & 255;
    float r = rel[(n - m + 255) * H_ + h];
    __nv_bfloat16 b1 = __float2bfloat16(r);
    float r2 = r - __bfloat162float(b1);
    bm1[i] = b1;
    bm2[i] = __float2bfloat16(r2);
}

// ---------------- LIF over T -> bf16 spikes, 4 elems/thread ----------------
__global__ __launch_bounds__(256) void attn_lif_pack(
    const float* __restrict__ In, __nv_bfloat16* __restrict__ Out)
{
    int i4 = (blockIdx.x * 256 + threadIdx.x) * 4;
    if (i4 >= BNROWS * C_) return;
    const __nv_bfloat16 one = __float2bfloat16(1.0f);
    const __nv_bfloat16 zero = __float2bfloat16(0.0f);
    float v0 = 0.f, v1 = 0.f, v2 = 0.f, v3 = 0.f;
    #pragma unroll
    for (int t = 0; t < 4; ++t) {
        float4 x = *(const float4*)(In + (size_t)t * BNROWS * C_ + i4);
        float h0 = v0 + (x.x - v0) * 0.5f;
        float h1 = v1 + (x.y - v1) * 0.5f;
        float h2 = v2 + (x.z - v2) * 0.5f;
        float h3 = v3 + (x.w - v3) * 0.5f;
        bool s0 = (h0 >= 1.0f), s1 = (h1 >= 1.0f), s2 = (h2 >= 1.0f), s3 = (h3 >= 1.0f);
        v0 = s0 ? 0.f : h0; v1 = s1 ? 0.f : h1;
        v2 = s2 ? 0.f : h2; v3 = s3 ? 0.f : h3;
        __nv_bfloat162 p0, p1;
        p0.x = s0 ? one : zero; p0.y = s1 ? one : zero;
        p1.x = s2 ? one : zero; p1.y = s3 ? one : zero;
        uint2 pk;
        pk.x = *(uint32_t*)&p0; pk.y = *(uint32_t*)&p1;
        *(uint2*)(Out + (size_t)t * BNROWS * C_ + i4) = pk;
    }
}

// ---------------- attention via HMMA, factorized S-path, aliased smem ----------------
// out[n][d] = SCALE * ( Q[n,:]·(K^T V)[:,d] + sum_m (bias1+bias2)[n][m] V[m][d] )
// smem layout (extent 96256 -> 2 CTA/SM):
//   VTB [0,24576) | KTB [24576,49152) | QB [57344,90112) | KTVB [90112,96256)
//   AB0 alias [24576,57344)   AB1 alias [57344,90112)
#define VTB_   (sbase + 0u)
#define KTB_   (sbase + 24576u)
#define QB_    (sbase + 57344u)
#define KTVB_  (sbase + 90112u)
__global__ __launch_bounds__(256, 2) void attn_mma(
    const __nv_bfloat16* __restrict__ Qs, const __nv_bfloat16* __restrict__ Ks,
    const __nv_bfloat16* __restrict__ Vs, const __nv_bfloat16* __restrict__ bm1,
    const __nv_bfloat16* __restrict__ bm2, float* __restrict__ AOut)
{
    extern __shared__ char smem_raw[];
    const uint32_t sbase = smem_u32(smem_raw);

    const int tid = threadIdx.x, wid = tid >> 5, l = tid & 31;
    const int bx = blockIdx.x;
    const int h = bx & 7;
    const int b = (bx >> 3) & 31;
    const int t = bx >> 8;
    const int r0 = t * BNROWS + b * N_;

    auto abuf = [&](int c) -> uint32_t {
        return (c & 1) ? (sbase + 57344u) : (sbase + 24576u);
    };
    auto issue_bias = [&](int c) {
        const __nv_bfloat16* bm = (c < 4) ? bm1 : bm2;
        int mc = c & 3;
        uint32_t dstb = abuf(c);
        #pragma unroll
        for (int it = 0; it < 8; ++it) {
            int g = tid + it * 256;            // 2048 granules
            int n = g >> 3, ch = g & 7;
            const __nv_bfloat16* src = bm + (size_t)((h * 256 + n) * 256 + mc * 64 + ch * 8);
            cp_async16(dstb + SWZ128((uint32_t)(n * 128 + ch * 16)), src);
        }
        cp_commit();
    };

    // prologue: Q tile (cp.async group 0)
    #pragma unroll
    for (int it = 0; it < 6; ++it) {
        int g = tid + it * 256;
        int n = g / 6, ch = g % 6;
        cp_async16(QB_ + SWZ128((uint32_t)(n * 128 + ch * 16)),
                   Qs + (size_t)(r0 + n) * C_ + h * D_ + ch * 8);
    }
    cp_commit();

    // scalar transpose K -> KTB_, V -> VTB_  ([d][m], pitch 512B, XOR swizzle)
    #pragma unroll
    for (int src_i = 0; src_i < 2; ++src_i) {
        const __nv_bfloat16* S = src_i ? Vs : Ks;
        char* base = smem_raw + (src_i ? 0 : 24576);
        #pragma unroll
        for (int it = 0; it < 6; ++it) {
            int g = tid + it * 256;
            int m = g / 6, dc = g % 6;
            uint4 v = *(const uint4*)(S + (size_t)(r0 + m) * C_ + h * D_ + dc * 8);
            const unsigned short* e = (const unsigned short*)&v;
            #pragma unroll
            for (int ee = 0; ee < 8; ++ee) {
                int d = dc * 8 + ee;
                *(unsigned short*)(base + d * 512 + ((m * 2) ^ ((d & 7) << 4))) = e[ee];
            }
        }
    }
    __syncthreads();

    // ---- stage 1: KTV[d'][d] = sum_m K[m][d'] V[m][d], write transposed ----
    for (int u = wid; u < 9; u += 8) {
        const int mt = u / 3, dp = u % 3;
        float ka[2][4];
        #pragma unroll
        for (int q = 0; q < 2; ++q)
            #pragma unroll
            for (int r = 0; r < 4; ++r) ka[q][r] = 0.f;
        for (int kidx = 0; kidx < 16; ++kidx) {
            uint32_t a0, a1, a2, a3, b0, b1, b2, b3;
            uint32_t arow = mt * 16 + (l & 15);
            uint32_t ko = (uint32_t)(kidx * 16 + (l >> 4) * 8) * 2;
            ldsm_x4(KTB_ + arow * 512 + (ko ^ ((arow & 7) << 4)), a0, a1, a2, a3);
            uint32_t brow = dp * 16 + (l & 7) + ((l >> 4) << 3);
            uint32_t kb = (uint32_t)(kidx * 16 + ((l >> 3) & 1) * 8) * 2;
            ldsm_x4(VTB_ + brow * 512 + (kb ^ ((brow & 7) << 4)), b0, b1, b2, b3);
            mma_bf16(ka[0][0], ka[0][1], ka[0][2], ka[0][3], a0, a1, a2, a3, b0, b1);
            mma_bf16(ka[1][0], ka[1][1], ka[1][2], ka[1][3], a0, a1, a2, a3, b2, b3);
        }
        int r = mt * 16 + (l >> 2);
        #pragma unroll
        for (int q = 0; q < 2; ++q) {
            int d = dp * 16 + q * 8 + (l & 3) * 2;
            __nv_bfloat16 v0 = __float2bfloat16(ka[q][0]);
            __nv_bfloat16 v1 = __float2bfloat16(ka[q][1]);
            __nv_bfloat16 v2 = __float2bfloat16(ka[q][2]);
            __nv_bfloat16 v3 = __float2bfloat16(ka[q][3]);
            char* kb = smem_raw + 90112;
            *(unsigned short*)(kb + SWZ128((uint32_t)((d + 0) * 128 + r * 2)))       = *(unsigned short*)&v0;
            *(unsigned short*)(kb + SWZ128((uint32_t)((d + 1) * 128 + r * 2)))       = *(unsigned short*)&v1;
            *(unsigned short*)(kb + SWZ128((uint32_t)((d + 0) * 128 + (r + 8) * 2))) = *(unsigned short*)&v2;
            *(unsigned short*)(kb + SWZ128((uint32_t)((d + 1) * 128 + (r + 8) * 2))) = *(unsigned short*)&v3;
        }
    }
    __syncthreads();           // KTB reads complete -> AB0 (alias) may be filled
    issue_bias(0);             // group 1 -> AB0

    float acc[2][6][4];
    #pragma unroll
    for (int mt = 0; mt < 2; ++mt)
        #pragma unroll
        for (int nt = 0; nt < 6; ++nt)
            #pragma unroll
            for (int r = 0; r < 4; ++r) acc[mt][nt][r] = 0.f;

    // ---- stage 2: acc += Q[n][d'] * KTV[d'][d]  (Q = group 0 done) ----
    asm volatile("cp.async.wait_group 1;");
    __syncthreads();
    #pragma unroll
    for (int kk = 0; kk < 3; ++kk) {
        uint32_t a[2][4], bfr[3][4];
        #pragma unroll
        for (int mt = 0; mt < 2; ++mt) {
            uint32_t row = wid * 32 + mt * 16 + (l & 15);
            uint32_t byte = row * 128 + (uint32_t)(kk * 16 + (l >> 4) * 8) * 2;
            ldsm_x4(QB_ + SWZ128(byte), a[mt][0], a[mt][1], a[mt][2], a[mt][3]);
        }
        #pragma unroll
        for (int bt = 0; bt < 3; ++bt) {
            uint32_t nrow = bt * 16 + (l & 7) + ((l >> 4) << 3);
            uint32_t byte = nrow * 128 + (uint32_t)(kk * 16 + ((l >> 3) & 1) * 8) * 2;
            ldsm_x4(KTVB_ + SWZ128(byte), bfr[bt][0], bfr[bt][1], bfr[bt][2], bfr[bt][3]);
        }
        #pragma unroll
        for (int mt = 0; mt < 2; ++mt)
            #pragma unroll
            for (int nt = 0; nt < 6; ++nt) {
                uint32_t b0 = bfr[nt >> 1][(nt & 1) * 2 + 0];
                uint32_t b1 = bfr[nt >> 1][(nt & 1) * 2 + 1];
                mma_bf16(acc[mt][nt][0], acc[mt][nt][1], acc[mt][nt][2], acc[mt][nt][3],
                         a[mt][0], a[mt][1], a[mt][2], a[mt][3], b0, b1);
            }
    }
    __syncthreads();           // QB/KTVB reads done -> AB1 (alias over QB) may be filled
    issue_bias(1);             // group 2 -> AB1

    // ---- bias chunks: acc += bias_chunk[n][64m] * V[m][d] ----
    for (int c = 0; c < 8; ++c) {
        const int mc = c & 3;
        if (c < 7) asm volatile("cp.async.wait_group 1;");
        else       asm volatile("cp.async.wait_group 0;");
        __syncthreads();

        const uint32_t ab = abuf(c);
        #pragma unroll
        for (int kk = 0; kk < 4; ++kk) {
            uint32_t a[2][4], bfr[3][4];
            #pragma unroll
            for (int mt = 0; mt < 2; ++mt) {
                uint32_t row = wid * 32 + mt * 16 + (l & 15);
                uint32_t byte = row * 128 + (uint32_t)(kk * 16 + (l >> 4) * 8) * 2;
                ldsm_x4(ab + SWZ128(byte), a[mt][0], a[mt][1], a[mt][2], a[mt][3]);
            }
            #pragma unroll
            for (int bt = 0; bt < 3; ++bt) {
                uint32_t nrow = bt * 16 + (l & 7) + ((l >> 4) << 3);
                uint32_t k = mc * 64 + kk * 16 + ((l >> 3) & 1) * 8;
                uint32_t addr = VTB_ + nrow * 512 + ((k * 2) ^ ((nrow & 7) << 4));
                ldsm_x4(addr, bfr[bt][0], bfr[bt][1], bfr[bt][2], bfr[bt][3]);
            }
            #pragma unroll
            for (int mt = 0; mt < 2; ++mt)
                #pragma unroll
                for (int nt = 0; nt < 6; ++nt) {
                    uint32_t b0 = bfr[nt >> 1][(nt & 1) * 2 + 0];
                    uint32_t b1 = bfr[nt >> 1][(nt & 1) * 2 + 1];
                    mma_bf16(acc[mt][nt][0], acc[mt][nt][1], acc[mt][nt][2], acc[mt][nt][3],
                             a[mt][0], a[mt][1], a[mt][2], a[mt][3], b0, b1);
                }
        }
        __syncthreads();
        if (c + 2 < 8) issue_bias(c + 2);
    }

    // epilogue: scale + store f32
    #pragma unroll
    for (int mt = 0; mt < 2; ++mt) {
        int n = wid * 32 + mt * 16 + (l >> 2);
        #pragma unroll
        for (int nt = 0; nt < 6; ++nt) {
            int d = nt * 8 + (l & 3) * 2;
            float* dst = AOut + (size_t)(r0 + n) * C_ + h * D_ + d;
            *(float2*)dst = make_float2(acc[mt][nt][0] * SCALE_, acc[mt][nt][1] * SCALE_);
            float* dst2 = dst + (size_t)8 * C_;
            *(float2*)dst2 = make_float2(acc[mt][nt][2] * SCALE_, acc[mt][nt][3] * SCALE_);
        }
    }
}

// ---------------- launch ----------------
extern "C" void kernel_launch(void* const* d_in, const int* in_sizes, int n_in,
                              void* d_out, int out_size)
{
    const float* x    = (const float*)d_in[0];
    const float* w_q  = (const float*)d_in[1];
    const float* w_k  = (const float*)d_in[2];
    const float* w_v  = (const float*)d_in[3];
    const float* w_p  = (const float*)d_in[4];
    const float* bn_q = (const float*)d_in[5];
    const float* bn_k = (const float*)d_in[6];
    const float* bn_v = (const float*)d_in[7];
    const float* bn_p = (const float*)d_in[8];
    const float* rel  = (const float*)d_in[9];
    float* out = (float*)d_out;

    __nv_bfloat16 *x1, *x2, *x3, *w1, *w2, *w3, *sqb, *skb, *svb, *aspk, *bm1, *bm2;
    float *attn;
    cudaGetSymbolAddress((void**)&x1, g_x1_);
    cudaGetSymbolAddress((void**)&x2, g_x2_);
    cudaGetSymbolAddress((void**)&x3, g_x3_);
    cudaGetSymbolAddress((void**)&w1, g_w1_);
    cudaGetSymbolAddress((void**)&w2, g_w2_);
    cudaGetSymbolAddress((void**)&w3, g_w3_);
    cudaGetSymbolAddress((void**)&sqb, g_sqb_);
    cudaGetSymbolAddress((void**)&skb, g_skb_);
    cudaGetSymbolAddress((void**)&svb, g_svb_);
    cudaGetSymbolAddress((void**)&attn, g_attn_);
    cudaGetSymbolAddress((void**)&aspk, g_aspk_);
    cudaGetSymbolAddress((void**)&bm1, g_bm1_);
    cudaGetSymbolAddress((void**)&bm2, g_bm2_);

    const int GSMEM6 = 98304;   // 2 x 48KB -> 2 CTA/SM
    const int GSMEM3 = 69632;   // 2 x 32KB stage + epilogue extent
    const int ASMEM  = 96256;   // -> 2 CTA/SM
    cudaFuncSetAttribute(hmma_gemm<6>, cudaFuncAttributeMaxDynamicSharedMemorySize, GSMEM6);
    cudaFuncSetAttribute(hmma_gemm<3>, cudaFuncAttributeMaxDynamicSharedMemorySize, GSMEM3);
    cudaFuncSetAttribute(attn_mma,     cudaFuncAttributeMaxDynamicSharedMemorySize, ASMEM);

    const int WW = C_ * C_;

    convert3<<<(NELEM / 4 + 255) / 256, 256>>>(x, x1, x2, x3, NELEM);
    W4 ws; ws.w[0] = w_q; ws.w[1] = w_k; ws.w[2] = w_v; ws.w[3] = w_p;
    convert3w<<<(4 * WW / 4 + 255) / 256, 256>>>(ws, w1, w2, w3);
    biasmat<<<(8 * 256 * 256 + 255) / 256, 256>>>(rel, bm1, bm2);

    // fused QKV GEMM + BN + LIF -> bf16 spikes
    GArgs ga;
    ga.A[0] = x1; ga.A[1] = x2; ga.A[2] = x3;
    ga.W[0][0] = w1 + 0 * WW; ga.W[0][1] = w2 + 0 * WW; ga.W[0][2] = w3 + 0 * WW;
    ga.W[1][0] = w1 + 1 * WW; ga.W[1][1] = w2 + 1 * WW; ga.W[1][2] = w3 + 1 * WW;
    ga.W[2][0] = w1 + 2 * WW; ga.W[2][1] = w2 + 2 * WW; ga.W[2][2] = w3 + 2 * WW;
    ga.bnp[0] = bn_q; ga.bnp[1] = bn_k; ga.bnp[2] = bn_v;
    ga.dst[0] = sqb; ga.dst[1] = skb; ga.dst[2] = svb;
    ga.mode[0] = 2; ga.mode[1] = 2; ga.mode[2] = 2;
    hmma_gemm<6><<<dim3(TBN / 128, 9), 256, GSMEM6>>>(ga);

    attn_mma<<<T_ * B_ * H_, 256, ASMEM>>>(sqb, skb, svb, bm1, bm2, attn);

    attn_lif_pack<<<(BNROWS * C_ / 4 + 255) / 256, 256>>>(attn, aspk);

    // proj GEMM (binary A exact in bf16 -> 3 products) writes final spikes
    GArgs gp;
    gp.A[0] = aspk; gp.A[1] = aspk; gp.A[2] = aspk;
    gp.W[0][0] = w1 + 3 * WW; gp.W[0][1] = w2 + 3 * WW; gp.W[0][2] = w3 + 3 * WW;
    gp.W[1][0] = gp.W[0][0]; gp.W[1][1] = gp.W[0][1]; gp.W[1][2] = gp.W[0][2];
    gp.W[2][0] = gp.W[0][0]; gp.W[2][1] = gp.W[0][1]; gp.W[2][2] = gp.W[0][2];
    gp.bnp[0] = bn_p; gp.bnp[1] = bn_p; gp.bnp[2] = bn_p;
    gp.dst[0] = out; gp.dst[1] = out; gp.dst[2] = out;
    gp.mode[0] = 0; gp.mode[1] = 0; gp.mode[2] = 0;
    hmma_gemm<3><<<dim3(TBN / 128, 3), 256, GSMEM3>>>(gp);
}